// round 9
// baseline (speedup 1.0000x reference)
#include <cuda_runtime.h>
#include <cstdint>

// ---------------------------------------------------------------------------
// GA (3,0,0) fused dense layer as one TF32 mma.sync GEMM.
//   out[k*B+b, d] = sum_j s(k,j) * ( X[i(k,j)*B+b, :] @ W[:, j*D+d] ) + bias[k*D+d]
// M=16384, N=2048, K=16384.
// R9: 256-thread CTA, 8 warps (2x4) of 64x32 tiles over the same 128x128 CTA
//     tile -> 64 accum regs/thread -> 2 CTAs/SM co-resident -> 4 warps/SMSP.
// ldmatrix.x4 A frags, 6-stage cp.async ring, one barrier per 2 k-tiles,
// signs via frag XOR, tf32-prerounded scratch.
// ---------------------------------------------------------------------------

#define NTHREADS 256
#define BK 16
#define NKT 1024               // 16384 / BK
#define NPAIRS 512
#define ASZ 2048               // A words per stage: 128*16
#define BSTRIDE 136            // B words per k-row (128 + 8 pad; 136 mod 32 == 8)
#define BSZ (16 * BSTRIDE)     // 2176 words
#define STAGE_W (ASZ + BSZ)    // 4224 words = 16896 B
#define STAGES 6
#define SMEM_BYTES (STAGES * STAGE_W * 4)   // 101376 B per CTA -> 2 CTAs/SM

// 128 MB scratch each: tf32-rounded copies of X and W
__device__ float Xc[16384 * 2048];
__device__ float Wc[2048 * 16384];

// ---------------- Cayley table (validated rounds 1/3/4/5/6/7/8) --------------
__device__ __constant__ int c_kij[64] = {
    0,1,2,3,4,5,6,7,  1,0,4,5,2,3,7,6,  2,4,0,6,1,7,3,5,  3,5,6,0,7,1,2,4,
    4,2,1,7,0,6,5,3,  5,3,7,1,6,0,4,2,  6,7,3,2,5,4,0,1,  7,6,5,4,3,2,1,0};
__device__ __constant__ float c_sij[64] = {
    1.f, 1.f, 1.f, 1.f, 1.f, 1.f, 1.f, 1.f,
    1.f, 1.f, 1.f, 1.f, 1.f, 1.f, 1.f, 1.f,
    1.f,-1.f, 1.f, 1.f,-1.f,-1.f, 1.f,-1.f,
    1.f,-1.f,-1.f, 1.f, 1.f,-1.f,-1.f, 1.f,
    1.f,-1.f, 1.f, 1.f,-1.f,-1.f, 1.f,-1.f,
    1.f,-1.f,-1.f, 1.f, 1.f,-1.f,-1.f, 1.f,
    1.f, 1.f,-1.f, 1.f,-1.f, 1.f,-1.f,-1.f,
    1.f, 1.f,-1.f, 1.f,-1.f, 1.f,-1.f,-1.f};

__device__ __forceinline__ void gather_info(int kblk, int j, int& ib, float& sg) {
    int ibv = 0; float sv = 1.f;
#pragma unroll
    for (int ii = 0; ii < 8; ++ii) {
        bool m = (c_kij[ii * 8 + j] == kblk);
        ibv = m ? ii : ibv;
        sv  = m ? c_sij[ii * 8 + j] : sv;
    }
    ib = ibv; sg = sv;
}

__device__ __forceinline__ uint32_t f2tf32(float f) {
    uint32_t r;
    asm("cvt.rna.tf32.f32 %0, %1;" : "=r"(r) : "f"(f));
    return r;
}

__device__ __forceinline__ void mma_tf32(float* d, const uint32_t* a, const uint32_t* b) {
    asm volatile(
        "mma.sync.aligned.m16n8k8.row.col.f32.tf32.tf32.f32 "
        "{%0,%1,%2,%3}, {%4,%5,%6,%7}, {%8,%9}, {%0,%1,%2,%3};"
        : "+f"(d[0]), "+f"(d[1]), "+f"(d[2]), "+f"(d[3])
        : "r"(a[0]), "r"(a[1]), "r"(a[2]), "r"(a[3]), "r"(b[0]), "r"(b[1]));
}

__device__ __forceinline__ void ldsm4(uint32_t* r, uint32_t addr) {
    asm volatile("ldmatrix.sync.aligned.m8n8.x4.shared.b16 {%0,%1,%2,%3}, [%4];"
        : "=r"(r[0]), "=r"(r[1]), "=r"(r[2]), "=r"(r[3]) : "r"(addr));
}

__device__ __forceinline__ uint32_t smem_u32(const void* p) {
    uint32_t a;
    asm("{ .reg .u64 t; cvta.to.shared.u64 t, %1; cvt.u32.u64 %0, t; }" : "=r"(a) : "l"(p));
    return a;
}

__device__ __forceinline__ void cp16(uint32_t dst, const float* src) {
    asm volatile("cp.async.cg.shared.global [%0], [%1], 16;" :: "r"(dst), "l"(src) : "memory");
}
#define CP_COMMIT()  asm volatile("cp.async.commit_group;" ::: "memory")
#define CP_WAIT(n)   asm volatile("cp.async.wait_group %0;" :: "n"(n) : "memory")

// ---------------------------------------------------------------------------
// Preprocess: round X and W to tf32 (RN) so the GEMM's HW truncation is exact.
__global__ __launch_bounds__(256)
void preconv_tf32(const float* __restrict__ X, const float* __restrict__ W)
{
    const size_t i = ((size_t)blockIdx.x * 256 + threadIdx.x) * 4;
    float4 x = *reinterpret_cast<const float4*>(X + i);
    x.x = __uint_as_float(f2tf32(x.x)); x.y = __uint_as_float(f2tf32(x.y));
    x.z = __uint_as_float(f2tf32(x.z)); x.w = __uint_as_float(f2tf32(x.w));
    *reinterpret_cast<float4*>(Xc + i) = x;
    float4 w = *reinterpret_cast<const float4*>(W + i);
    w.x = __uint_as_float(f2tf32(w.x)); w.y = __uint_as_float(f2tf32(w.y));
    w.z = __uint_as_float(f2tf32(w.z)); w.w = __uint_as_float(f2tf32(w.w));
    *reinterpret_cast<float4*>(Wc + i) = w;
}

// ---------------------------------------------------------------------------
__global__ __launch_bounds__(NTHREADS, 2)
void ga_tf32_mma7(const float* __restrict__ bias,  // [16384]
                  float* __restrict__ out)         // [16384, 2048]
{
    extern __shared__ uint32_t sm[];
    const uint32_t sb = smem_u32(sm);

    const int tid  = threadIdx.x;
    const int wid  = tid >> 5;
    const int lane = tid & 31;
    const int q    = lane & 3;
    const int g    = lane >> 2;
    const int wm   = wid >> 2;      // 0..1 (M warps, 64 rows each)
    const int wn   = wid & 3;       // 0..3 (N warps, 32 cols each)

    const int bn   = blockIdx.x;    // 0..15  N tiles (128 wide)
    const int bm   = blockIdx.y;    // 0..127 M tiles (128 tall)
    const int kblk = bm >> 4;       // output blade
    const int rloc = (bm & 15) * 128;

    int      ibA[8];
    uint32_t signbits = 0;
#pragma unroll
    for (int j = 0; j < 8; ++j) {
        int ib; float sg;
        gather_info(kblk, j, ib, sg);
        ibA[j] = ib;
        if (sg < 0.f) signbits |= (1u << j);
    }

    float acc[4][4][4];                 // 64 accum regs/thread
#pragma unroll
    for (int f = 0; f < 4; ++f)
#pragma unroll
        for (int n = 0; n < 4; ++n)
#pragma unroll
            for (int e = 0; e < 4; ++e) acc[f][n][e] = 0.f;

    // ---- ldmatrix per-lane address precompute (A fragments) ----
    const int sub    = lane >> 3;
    const int hi     = sub >> 1;
    const int rowoff = (lane & 7) + (sub & 1) * 8;
    uint32_t rbyte[4];
    int      sx[4];
#pragma unroll
    for (int f = 0; f < 4; ++f) {
        const int r = wm * 64 + f * 16 + rowoff;
        rbyte[f] = (uint32_t)(r * 64);
        sx[f]    = (r >> 1) & 3;
    }

    // cp.async thread mappings (256 threads)
    const int a_m = tid >> 2;        // 0..63 (+64)
    const int a_c = tid & 3;
    const int b_k = tid >> 5;        // 0..7  (+8)
    const int b_n = (tid & 31) * 4;

    auto issue_tile = [&](int kt) {
        const int s  = kt % STAGES;
        const int j  = kt >> 7;
        const int c0 = (kt & 127) * BK;
        const uint32_t As = sb + (uint32_t)(s * STAGE_W * 4);
        const uint32_t Bs = As + ASZ * 4;
        const float* Ap = Xc + ((size_t)(ibA[j] * 2048 + rloc)) * 2048 + c0 + a_c * 4;
#pragma unroll
        for (int i = 0; i < 2; ++i) {
            const int m  = a_m + 64 * i;
            const int ch = a_c ^ ((m >> 1) & 3);
            cp16(As + (uint32_t)((m * 16 + ch * 4) * 4), Ap + (size_t)m * 2048);
        }
        const float* Bp = Wc + (size_t)c0 * 16384 + (size_t)j * 2048 + bn * 128 + b_n;
#pragma unroll
        for (int i = 0; i < 2; ++i)
            cp16(Bs + (uint32_t)(((b_k + 8 * i) * BSTRIDE + b_n) * 4),
                 Bp + (size_t)(b_k + 8 * i) * 16384);
    };

    auto compute_tile = [&](int kt) {
        const int s = kt % STAGES;
        const uint32_t AsAddr = sb + (uint32_t)(s * STAGE_W * 4);
        const uint32_t* Bs = sm + s * STAGE_W + ASZ;
        const uint32_t  smask = ((signbits >> (kt >> 7)) & 1u) << 31;
#pragma unroll
        for (int ks = 0; ks < 2; ++ks) {
            uint32_t afr[4][4], bfr[4][2];
#pragma unroll
            for (int f = 0; f < 4; ++f) {
                const int ch = (2 * ks + hi) ^ sx[f];
                ldsm4(afr[f], AsAddr + rbyte[f] + (uint32_t)(ch * 16));
            }
#pragma unroll
            for (int f = 0; f < 4; ++f) {
                afr[f][0] ^= smask; afr[f][1] ^= smask;
                afr[f][2] ^= smask; afr[f][3] ^= smask;
            }
#pragma unroll
            for (int nf = 0; nf < 4; ++nf) {
                const int n0 = wn * 32 + nf * 8 + g;
                bfr[nf][0] = Bs[(ks * 8 + q    ) * BSTRIDE + n0];
                bfr[nf][1] = Bs[(ks * 8 + q + 4) * BSTRIDE + n0];
            }
#pragma unroll
            for (int f = 0; f < 4; ++f)
#pragma unroll
                for (int nf = 0; nf < 4; ++nf)
                    mma_tf32(acc[f][nf], afr[f], bfr[nf]);
        }
    };

    // prologue: pairs 0 and 1 (tiles 0..3), one commit group per pair
    issue_tile(0); issue_tile(1); CP_COMMIT();
    issue_tile(2); issue_tile(3); CP_COMMIT();

    for (int p = 0; p < NPAIRS; ++p) {
        if (p < NPAIRS - 1) { CP_WAIT(1); } else { CP_WAIT(0); }
        __syncthreads();     // single barrier per pair; protects stage reuse

        if (p + 2 < NPAIRS) {
            issue_tile(2 * p + 4);
            issue_tile(2 * p + 5);
            CP_COMMIT();
        }

        compute_tile(2 * p);
        compute_tile(2 * p + 1);
        // no trailing barrier: next iteration's writes target pair p-1's
        // stages, which every warp finished before this iteration's barrier.
    }

    // ---- epilogue: add blade bias, store ----
    const int ccol = bn * 128 + wn * 32;
    const float* bp = bias + (size_t)kblk * 2048 + ccol;

#pragma unroll
    for (int nf = 0; nf < 4; ++nf) {
        const int cn = nf * 8 + 2 * q;
        const float b0 = bp[cn], b1 = bp[cn + 1];
#pragma unroll
        for (int f = 0; f < 4; ++f) {
            const int r0 = bm * 128 + wm * 64 + f * 16 + g;
            float2 lo  = make_float2(acc[f][nf][0] + b0, acc[f][nf][1] + b1);
            float2 hi2 = make_float2(acc[f][nf][2] + b0, acc[f][nf][3] + b1);
            *reinterpret_cast<float2*>(out + (size_t)r0 * 2048 + ccol + cn)       = lo;
            *reinterpret_cast<float2*>(out + (size_t)(r0 + 8) * 2048 + ccol + cn) = hi2;
        }
    }
}

extern "C" void kernel_launch(void* const* d_in, const int* in_sizes, int n_in,
                              void* d_out, int out_size)
{
    const float* X    = (const float*)d_in[0];
    const float* W    = (const float*)d_in[1];
    const float* bias = (const float*)d_in[2];
    float* out        = (float*)d_out;

    preconv_tf32<<<32768, 256>>>(X, W);

    cudaFuncSetAttribute(ga_tf32_mma7, cudaFuncAttributeMaxDynamicSharedMemorySize, SMEM_BYTES);
    dim3 grid(16, 128);
    ga_tf32_mma7<<<grid, NTHREADS, SMEM_BYTES>>>(bias, out);
}